// round 15
// baseline (speedup 1.0000x reference)
#include <cuda_runtime.h>
#include <math.h>

// Problem constants (fixed shapes per reference)
#define BB 4
#define NN 8192
#define KK 16
#define NPATCH 32
#define PP 256            // points per patch
#define NTILE 512         // 16-point tiles per batch
#define TSZ 16            // tile size
#define NCELL 4096        // 16^3 Morton cells
#define BCAP 32           // per-thread hit buffer capacity

// ---------------- scratch (no allocations allowed) ----------------
__device__ float4 g_sorted[BB * NN];       // spatially sorted points (+|c|^2 in .w)
__device__ int    g_perm[BB * NN];         // sorted slot -> original index
__device__ float  g_nrm_abs[BB * NN * 3];  // |global normal| (original index order)
__device__ float  g_sv[BB * NN];           // global surface variance
__device__ double g_pn[BB * NPATCH];       // per-patch partial normal loss
__device__ double g_psv[BB * NPATCH];      // per-patch partial surfvar loss
__device__ unsigned int g_done;            // patch-block arrival counter
__device__ int    g_hist[BB * NCELL];      // per-batch cell histogram (zeroed after use)
__device__ int    g_off[BB * NCELL];       // per-batch exclusive cell offsets
__device__ int    g_cnt[BB * NCELL];       // per-batch scatter counters (zeroed before use)

// ---------------- sorted insertion into ascending top-16 ----------------
__device__ __forceinline__ void insert16(float v, int j, float (&ds)[KK], int (&is)[KK]) {
    bool pt = v < ds[KK - 1];
#pragma unroll
    for (int t = KK - 1; t >= 1; --t) {
        bool pm = v < ds[t - 1];
        float nv = pm ? ds[t - 1] : v;
        int   ni = pm ? is[t - 1] : j;
        ds[t] = pt ? nv : ds[t];
        is[t] = pt ? ni : is[t];
        pt = pm;
    }
    ds[0] = pt ? v : ds[0];
    is[0] = pt ? j : is[0];
}

// ---------------- analytic 3x3 symmetric eigensolver ----------------
__device__ __forceinline__ void eig3(float a00, float a01, float a02,
                                     float a11, float a12, float a22,
                                     float &l0, float &l1, float &l2,
                                     float &vx, float &vy, float &vz) {
    float q = (a00 + a11 + a22) * (1.0f / 3.0f);
    float b00 = a00 - q, b11 = a11 - q, b22 = a22 - q;
    float p1 = a01 * a01 + a02 * a02 + a12 * a12;
    float p2 = b00 * b00 + b11 * b11 + b22 * b22 + 2.0f * p1;
    if (p2 <= 1e-30f) {
        l0 = l1 = l2 = q;
        vx = 1.0f; vy = 0.0f; vz = 0.0f;
        return;
    }
    float p = sqrtf(p2 * (1.0f / 6.0f));
    float ip = 1.0f / p;
    float c00 = b00 * ip, c11 = b11 * ip, c22 = b22 * ip;
    float c01 = a01 * ip, c02 = a02 * ip, c12 = a12 * ip;
    float det = c00 * (c11 * c22 - c12 * c12)
              - c01 * (c01 * c22 - c12 * c02)
              + c02 * (c01 * c12 - c11 * c02);
    float r = 0.5f * det;
    r = fminf(1.0f, fmaxf(-1.0f, r));
    float phi = acosf(r) * (1.0f / 3.0f);
    float two_p = 2.0f * p;
    l2 = q + two_p * cosf(phi);                          // largest
    l0 = q + two_p * cosf(phi + 2.0943951023931953f);    // smallest
    l1 = 3.0f * q - l2 - l0;

    float m00 = a00 - l0, m11 = a11 - l0, m22 = a22 - l0;
    float x0 = a01 * a12 - a02 * m11;
    float y0 = a02 * a01 - m00 * a12;
    float z0 = m00 * m11 - a01 * a01;
    float x1 = a01 * m22 - a02 * a12;
    float y1 = a02 * a02 - m00 * m22;
    float z1 = m00 * a12 - a01 * a02;
    float x2 = m11 * m22 - a12 * a12;
    float y2 = a12 * a02 - a01 * m22;
    float z2 = a01 * a12 - m11 * a02;
    float n0 = x0 * x0 + y0 * y0 + z0 * z0;
    float n1 = x1 * x1 + y1 * y1 + z1 * z1;
    float n2 = x2 * x2 + y2 * y2 + z2 * z2;
    float bx = x0, by = y0, bz = z0, bn = n0;
    if (n1 > bn) { bx = x1; by = y1; bz = z1; bn = n1; }
    if (n2 > bn) { bx = x2; by = y2; bz = z2; bn = n2; }
    if (bn < 1e-40f) { bx = 1.0f; by = 0.0f; bz = 0.0f; bn = 1.0f; }
    float inv = rsqrtf(bn);
    vx = bx * inv; vy = by * inv; vz = bz * inv;
}

// ---------------- covariance of centered neighbor set + eig ----------------
__device__ __forceinline__ void cov_eig(const float4* __restrict__ sh,
                                        float qx, float qy, float qz,
                                        const int (&is)[KK],
                                        float &l0, float &l1, float &l2,
                                        float &vx, float &vy, float &vz) {
    float a00 = 0.f, a01 = 0.f, a02 = 0.f, a11 = 0.f, a12 = 0.f, a22 = 0.f;
#pragma unroll
    for (int t = 0; t < KK; ++t) {
        float4 nb = sh[is[t]];
        float dx = nb.x - qx, dy = nb.y - qy, dz = nb.z - qz;
        a00 = fmaf(dx, dx, a00); a01 = fmaf(dx, dy, a01); a02 = fmaf(dx, dz, a02);
        a11 = fmaf(dy, dy, a11); a12 = fmaf(dy, dz, a12); a22 = fmaf(dz, dz, a22);
    }
    eig3(a00, a01, a02, a11, a12, a22, l0, l1, l2, vx, vy, vz);
}

// ---------------- Morton cell code (12-bit, 16^3 over [-4,4]) ----------------
__device__ __forceinline__ unsigned int morton12(float x, float y, float z) {
    int ux = min(15, max(0, (int)((x + 4.0f) * 2.0f)));
    int uy = min(15, max(0, (int)((y + 4.0f) * 2.0f)));
    int uz = min(15, max(0, (int)((z + 4.0f) * 2.0f)));
    unsigned int code = 0;
#pragma unroll
    for (int b = 0; b < 4; ++b) {
        code |= ((ux >> b) & 1) << (3 * b + 0);
        code |= ((uy >> b) & 1) << (3 * b + 1);
        code |= ((uz >> b) & 1) << (3 * b + 2);
    }
    return code;
}

// ---------------- kernel 0a: histogram (16 blocks) ----------------
__global__ void __launch_bounds__(512)
hist_kernel(const float* __restrict__ pc) {
    const int b     = blockIdx.x >> 2;        // batch
    const int chunk = blockIdx.x & 3;         // quarter of the batch
    const float* base = pc + (size_t)b * NN * 3;
    const int t = threadIdx.x;

    if (blockIdx.x == 0 && t == 0) g_done = 0;   // reset arrival counter

    const int i0 = chunk * (NN / 4);
    for (int i = i0 + t; i < i0 + NN / 4; i += 512) {
        float x = base[i * 3 + 0];
        float y = base[i * 3 + 1];
        float z = base[i * 3 + 2];
        atomicAdd(&g_hist[b * NCELL + morton12(x, y, z)], 1);
    }
}

// ---------------- kernel 0b: scan offsets + re-zero hist/cnt ----------------
__global__ void __launch_bounds__(512)
scan_kernel(const float* __restrict__ pc) {
    __shared__ int part[512];
    const int b = blockIdx.x;
    const int t = threadIdx.x;

    int h[8];
    int s = 0;
#pragma unroll
    for (int u = 0; u < 8; ++u) { h[u] = g_hist[b * NCELL + t * 8 + u]; s += h[u]; }
    part[t] = s;
    __syncthreads();
    for (int o = 1; o < 512; o <<= 1) {
        int v = (t >= o) ? part[t - o] : 0;
        __syncthreads();
        part[t] += v;
        __syncthreads();
    }
    int basev = part[t] - s;
#pragma unroll
    for (int u = 0; u < 8; ++u) {
        g_off[b * NCELL + t * 8 + u] = basev;
        basev += h[u];
        g_hist[b * NCELL + t * 8 + u] = 0;   // re-zero for next replay
        g_cnt[b * NCELL + t * 8 + u] = 0;    // zero scatter counters
    }
}

// ---------------- kernel 0c: scatter (16 blocks) ----------------
__global__ void __launch_bounds__(512)
scatter_kernel(const float* __restrict__ pc) {
    const int b     = blockIdx.x >> 2;
    const int chunk = blockIdx.x & 3;
    const float* base = pc + (size_t)b * NN * 3;
    const int t = threadIdx.x;

    const int i0 = chunk * (NN / 4);
    for (int i = i0 + t; i < i0 + NN / 4; i += 512) {
        float x = base[i * 3 + 0];
        float y = base[i * 3 + 1];
        float z = base[i * 3 + 2];
        unsigned int c = morton12(x, y, z);
        int pos = g_off[b * NCELL + c] + atomicAdd(&g_cnt[b * NCELL + c], 1);
        float c2 = __fadd_rn(__fadd_rn(__fmul_rn(x, x), __fmul_rn(y, y)), __fmul_rn(z, z));
        g_sorted[b * NN + pos] = make_float4(x, y, z, c2);
        g_perm[b * NN + pos] = i;
    }
}

// ---------------- kernel 1: global kNN, linear 4-wide tile sweep + seed ------
// smem layout: float4 pts[8192] | float4 boxmin[512] | float4 boxmax[512]
//              | float mds[256*16] | int mis[256*16]   (176 KB)
extern __shared__ unsigned char smem_raw[];

__global__ void __launch_bounds__(512, 1)
knn_global_kernel(const float* __restrict__ pc) {
    float4* sh     = (float4*)smem_raw;
    float4* boxmin = (float4*)(smem_raw + NN * 16);
    float4* boxmax = (float4*)(smem_raw + NN * 16 + NTILE * 16);
    float*  mds    = (float*)(smem_raw + NN * 16 + 2 * NTILE * 16);
    int*    mis    = (int*)(smem_raw + NN * 16 + 2 * NTILE * 16 + 256 * KK * 4);

    const int b = blockIdx.y;
    const float4* gs = g_sorted + b * NN;

    // stage sorted points
    for (int i = threadIdx.x; i < NN; i += 512) sh[i] = gs[i];
    __syncthreads();

    // tile AABBs (512 tiles, one per thread)
    {
        const int T = threadIdx.x;
        float4 p0 = sh[T * TSZ];
        float mnx = p0.x, mny = p0.y, mnz = p0.z;
        float mxx = p0.x, mxy = p0.y, mxz = p0.z;
#pragma unroll
        for (int u = 1; u < TSZ; ++u) {
            float4 p = sh[T * TSZ + u];
            mnx = fminf(mnx, p.x); mny = fminf(mny, p.y); mnz = fminf(mnz, p.z);
            mxx = fmaxf(mxx, p.x); mxy = fmaxf(mxy, p.y); mxz = fmaxf(mxz, p.z);
        }
        boxmin[T] = make_float4(mnx, mny, mnz, 0.f);
        boxmax[T] = make_float4(mxx, mxy, mxz, 0.f);
    }
    __syncthreads();

    const int q    = threadIdx.x & 255;       // query slot within block
    const int half = threadIdx.x >> 8;        // tile-parity this thread scans
    const int qi   = blockIdx.x * 256 + q;    // sorted index of query

    float4 qp = sh[qi];
    const float qx = qp.x, qy = qp.y, qz = qp.z, q2 = qp.w;
    const float nqx = -2.0f * qx, nqy = -2.0f * qy, nqz = -2.0f * qz;

    // --- seed: own tile has exactly 16 points -> max of their computed rank
    //     keys is a valid upper bound on the final 16th key. Ladder-free.
    float wmax = -3.4e38f;
    {
        const int jb0 = (qi >> 4) << 4;
#pragma unroll
        for (int u = 0; u < TSZ; ++u) {
            float4 c = sh[jb0 + u];
            float d = fmaf(c.x, nqx, fmaf(c.y, nqy, fmaf(c.z, nqz, c.w)));
            wmax = fmaxf(wmax, d);
        }
    }
    // prune threshold in true-d2 space, inflated for rank-key rounding slack
    float wmax_d2 = fmaf(fabsf(wmax + q2), 1e-4f, wmax + q2) + 1e-6f;

    float ds[KK];
    int   is[KK];
#pragma unroll
    for (int t = 0; t < KK; ++t) { ds[t] = 3.4e38f; is[t] = 0; }

    float bufd[BCAP];
    int   bufi[BCAP];
    int   cnt = 0;

    // --- linear 4-wide sweep over this parity's 256 tiles.
    // Order is irrelevant for correctness (wmax monotone, seed already tight);
    // 4 independent AABB tests per vote maximizes MLP and minimizes votes.
    for (int T0 = half; T0 < NTILE; T0 += 8) {
        float4 bmn0 = boxmin[T0 + 0], bmx0 = boxmax[T0 + 0];
        float4 bmn1 = boxmin[T0 + 2], bmx1 = boxmax[T0 + 2];
        float4 bmn2 = boxmin[T0 + 4], bmx2 = boxmax[T0 + 4];
        float4 bmn3 = boxmin[T0 + 6], bmx3 = boxmax[T0 + 6];

        float dx0 = fmaxf(fmaxf(bmn0.x - qx, qx - bmx0.x), 0.f);
        float dy0 = fmaxf(fmaxf(bmn0.y - qy, qy - bmx0.y), 0.f);
        float dz0 = fmaxf(fmaxf(bmn0.z - qz, qz - bmx0.z), 0.f);
        float d20 = fmaf(dx0, dx0, fmaf(dy0, dy0, dz0 * dz0));

        float dx1 = fmaxf(fmaxf(bmn1.x - qx, qx - bmx1.x), 0.f);
        float dy1 = fmaxf(fmaxf(bmn1.y - qy, qy - bmx1.y), 0.f);
        float dz1 = fmaxf(fmaxf(bmn1.z - qz, qz - bmx1.z), 0.f);
        float d21 = fmaf(dx1, dx1, fmaf(dy1, dy1, dz1 * dz1));

        float dx2 = fmaxf(fmaxf(bmn2.x - qx, qx - bmx2.x), 0.f);
        float dy2 = fmaxf(fmaxf(bmn2.y - qy, qy - bmx2.y), 0.f);
        float dz2 = fmaxf(fmaxf(bmn2.z - qz, qz - bmx2.z), 0.f);
        float d22 = fmaf(dx2, dx2, fmaf(dy2, dy2, dz2 * dz2));

        float dx3 = fmaxf(fmaxf(bmn3.x - qx, qx - bmx3.x), 0.f);
        float dy3 = fmaxf(fmaxf(bmn3.y - qy, qy - bmx3.y), 0.f);
        float dz3 = fmaxf(fmaxf(bmn3.z - qz, qz - bmx3.z), 0.f);
        float d23 = fmaf(dx3, dx3, fmaf(dy3, dy3, dz3 * dz3));

        bool h0 = d20 < wmax_d2;
        bool h1 = d21 < wmax_d2;
        bool h2 = d22 < wmax_d2;
        bool h3 = d23 < wmax_d2;

        if (__any_sync(0xffffffffu, h0 | h1 | h2 | h3)) {
#pragma unroll
            for (int k = 0; k < 4; ++k) {
                bool hk = (k == 0) ? h0 : (k == 1) ? h1 : (k == 2) ? h2 : h3;
                if (__any_sync(0xffffffffu, hk)) {
                    const int jb = (T0 + 2 * k) << 4;
#pragma unroll
                    for (int u = 0; u < TSZ; ++u) {
                        float4 c = sh[jb + u];
                        float d = fmaf(c.x, nqx, fmaf(c.y, nqy, fmaf(c.z, nqz, c.w)));
                        if (d <= wmax) {    // <= keeps the seed-boundary point
                            bufd[cnt] = d;
                            bufi[cnt] = jb + u;
                            ++cnt;
                        }
                    }
                    if (__any_sync(0xffffffffu, cnt > BCAP - TSZ)) {
#pragma unroll
                        for (int t = 0; t < BCAP; ++t) {
                            if (t < cnt) insert16(bufd[t], bufi[t], ds, is);
                        }
                        cnt = 0;
                        wmax = fminf(wmax, ds[KK - 1]);
                        wmax_d2 = fmaf(fabsf(wmax + q2), 1e-4f, wmax + q2) + 1e-6f;
                    }
                }
            }
        }
    }
    // drain remaining buffered hits
#pragma unroll
    for (int t = 0; t < BCAP; ++t) {
        if (t < cnt) insert16(bufd[t], bufi[t], ds, is);
    }

    // merge the two parity halves
    if (half) {
#pragma unroll
        for (int t = 0; t < KK; ++t) {
            mds[q * KK + t] = ds[t];
            mis[q * KK + t] = is[t];
        }
    }
    __syncthreads();

    if (!half) {
#pragma unroll
        for (int t = 0; t < KK; ++t) {
            float v = mds[q * KK + t];
            if (v < ds[KK - 1]) insert16(v, mis[q * KK + t], ds, is);
        }

        float l0, l1, l2, vx, vy, vz;
        cov_eig(sh, qx, qy, qz, is, l0, l1, l2, vx, vy, vz);

        const int gi = b * NN + g_perm[b * NN + qi];   // original point index
        g_nrm_abs[gi * 3 + 0] = fabsf(vx);
        g_nrm_abs[gi * 3 + 1] = fabsf(vy);
        g_nrm_abs[gi * 3 + 2] = fabsf(vz);
        g_sv[gi] = l0 / (l0 + l1 + l2);
    }
}

// ---------------- kernel 2: patch kNN + eig + loss + folded final reduction ---
__global__ void __launch_bounds__(PP, 4)
knn_patch_kernel(const float* __restrict__ pc, float* __restrict__ out) {
    __shared__ float4 shp[PP];
    __shared__ double s_n[PP];
    __shared__ double s_sv[PP];
    __shared__ bool   s_last;

    const int patch = blockIdx.x;              // 0 .. BB*NPATCH-1
    const float* base = pc + (size_t)patch * PP * 3;
    const int t = threadIdx.x;

    {
        float x = base[t * 3 + 0];
        float y = base[t * 3 + 1];
        float z = base[t * 3 + 2];
        float c2 = __fadd_rn(__fadd_rn(__fmul_rn(x, x), __fmul_rn(y, y)), __fmul_rn(z, z));
        shp[t] = make_float4(x, y, z, c2);
    }
    __syncthreads();

    float4 qp = shp[t];
    const float nqx = -2.0f * qp.x, nqy = -2.0f * qp.y, nqz = -2.0f * qp.z;

    float ds[KK];
    int   is[KK];
#pragma unroll
    for (int k = 0; k < KK; ++k) { ds[k] = 3.4e38f; is[k] = 0; }

    {
        float bufd[BCAP];
        int   bufi[BCAP];
        int   cnt = 0;
        float wmax = 3.4e38f;
        for (int j = 0; j < PP; j += 8) {
            float d[8];
#pragma unroll
            for (int u = 0; u < 8; ++u) {
                float4 c = shp[j + u];
                d[u] = fmaf(c.x, nqx, fmaf(c.y, nqy, fmaf(c.z, nqz, c.w)));
            }
            float m = fminf(fminf(fminf(d[0], d[1]), fminf(d[2], d[3])),
                            fminf(fminf(d[4], d[5]), fminf(d[6], d[7])));
            if (m < wmax) {
#pragma unroll
                for (int u = 0; u < 8; ++u) {
                    if (d[u] < wmax) { bufd[cnt] = d[u]; bufi[cnt] = j + u; ++cnt; }
                }
            }
            if (__any_sync(0xffffffffu, cnt > BCAP - 8)) {
#pragma unroll
                for (int s = 0; s < BCAP; ++s) {
                    if (s < cnt) insert16(bufd[s], bufi[s], ds, is);
                }
                cnt = 0;
                wmax = ds[KK - 1];
            }
        }
#pragma unroll
        for (int s = 0; s < BCAP; ++s) {
            if (s < cnt) insert16(bufd[s], bufi[s], ds, is);
        }
    }

    float l0, l1, l2, vx, vy, vz;
    cov_eig(shp, qp.x, qp.y, qp.z, is, l0, l1, l2, vx, vy, vz);

    const int gi = patch * PP + t;   // == flat [B, N] original index
    float svp = l0 / (l0 + l1 + l2);

    float gx = g_nrm_abs[gi * 3 + 0];
    float gy = g_nrm_abs[gi * 3 + 1];
    float gz = g_nrm_abs[gi * 3 + 2];
    float ex = fabsf(vx) - gx;
    float ey = fabsf(vy) - gy;
    float ez = fabsf(vz) - gz;
    float ln = sqrtf(ex * ex + ey * ey + ez * ez);

    float dsv = svp - g_sv[gi];
    float lsv = dsv * dsv;

    // deterministic block reduction
    s_n[t]  = (double)ln;
    s_sv[t] = (double)lsv;
    __syncthreads();
#pragma unroll
    for (int s = PP / 2; s > 0; s >>= 1) {
        if (t < s) { s_n[t] += s_n[t + s]; s_sv[t] += s_sv[t + s]; }
        __syncthreads();
    }
    if (t == 0) {
        g_pn[patch]  = s_n[0];
        g_psv[patch] = s_sv[0];
        __threadfence();
        unsigned int v = atomicAdd(&g_done, 1);
        s_last = (v == BB * NPATCH - 1);
    }
    __syncthreads();

    // last-arriving block performs the deterministic final reduction
    if (s_last) {
        if (t < BB * NPATCH) {
            s_n[t]  = __ldcg(&g_pn[t]);     // bypass L1: other SMs wrote these
            s_sv[t] = __ldcg(&g_psv[t]);
        } else {
            s_n[t] = 0.0; s_sv[t] = 0.0;
        }
        __syncthreads();
#pragma unroll
        for (int s = PP / 2; s > 0; s >>= 1) {
            if (t < s) { s_n[t] += s_n[t + s]; s_sv[t] += s_sv[t + s]; }
            __syncthreads();
        }
        if (t == 0) {
            const double inv = 1.0 / (double)(BB * NN);
            out[0] = (float)(s_n[0]  * inv);   // * W_NORMAL (=1)
            out[1] = (float)(s_sv[0] * inv);   // * W_SURFVAR (=1)
        }
    }
}

// ---------------- launcher ----------------
extern "C" void kernel_launch(void* const* d_in, const int* in_sizes, int n_in,
                              void* d_out, int out_size) {
    (void)in_sizes; (void)n_in; (void)out_size;
    const float* pc = (const float*)d_in[0];
    float* out = (float*)d_out;

    const int smem_bytes = NN * 16 + 2 * NTILE * 16 + 256 * KK * 8;  // 176 KB
    cudaFuncSetAttribute(knn_global_kernel,
                         cudaFuncAttributeMaxDynamicSharedMemorySize,
                         smem_bytes);

    hist_kernel<<<BB * 4, 512>>>(pc);
    scan_kernel<<<BB, 512>>>(pc);
    scatter_kernel<<<BB * 4, 512>>>(pc);
    dim3 g1(NN / 256, BB);
    knn_global_kernel<<<g1, 512, smem_bytes>>>(pc);
    knn_patch_kernel<<<BB * NPATCH, PP>>>(pc, out);
}

// round 16
// speedup vs baseline: 3.2087x; 3.2087x over previous
#include <cuda_runtime.h>
#include <math.h>

// Problem constants (fixed shapes per reference)
#define BB 4
#define NN 8192
#define KK 16
#define NPATCH 32
#define PP 256            // points per patch
#define NTILE 512         // 16-point tiles per batch
#define TSZ 16            // tile size
#define NCELL 4096        // 16^3 Morton cells
#define BCAP 32           // per-thread hit buffer capacity

// ---------------- scratch (no allocations allowed) ----------------
__device__ float4 g_sorted[BB * NN];       // spatially sorted points (+|c|^2 in .w)
__device__ int    g_perm[BB * NN];         // sorted slot -> original index
__device__ float  g_nrm_abs[BB * NN * 3];  // |global normal| (original index order)
__device__ float  g_sv[BB * NN];           // global surface variance
__device__ double g_pn[BB * NPATCH];       // per-patch partial normal loss
__device__ double g_psv[BB * NPATCH];      // per-patch partial surfvar loss
__device__ unsigned int g_done;            // patch-block arrival counter
__device__ int    g_hist[BB * NCELL];      // per-batch cell histogram (zeroed after use)
__device__ int    g_off[BB * NCELL];       // per-batch exclusive cell offsets
__device__ int    g_cnt[BB * NCELL];       // per-batch scatter counters (zeroed before use)

// ---------------- sorted insertion into ascending top-16 ----------------
__device__ __forceinline__ void insert16(float v, int j, float (&ds)[KK], int (&is)[KK]) {
    bool pt = v < ds[KK - 1];
#pragma unroll
    for (int t = KK - 1; t >= 1; --t) {
        bool pm = v < ds[t - 1];
        float nv = pm ? ds[t - 1] : v;
        int   ni = pm ? is[t - 1] : j;
        ds[t] = pt ? nv : ds[t];
        is[t] = pt ? ni : is[t];
        pt = pm;
    }
    ds[0] = pt ? v : ds[0];
    is[0] = pt ? j : is[0];
}

// ---------------- analytic 3x3 symmetric eigensolver ----------------
__device__ __forceinline__ void eig3(float a00, float a01, float a02,
                                     float a11, float a12, float a22,
                                     float &l0, float &l1, float &l2,
                                     float &vx, float &vy, float &vz) {
    float q = (a00 + a11 + a22) * (1.0f / 3.0f);
    float b00 = a00 - q, b11 = a11 - q, b22 = a22 - q;
    float p1 = a01 * a01 + a02 * a02 + a12 * a12;
    float p2 = b00 * b00 + b11 * b11 + b22 * b22 + 2.0f * p1;
    if (p2 <= 1e-30f) {
        l0 = l1 = l2 = q;
        vx = 1.0f; vy = 0.0f; vz = 0.0f;
        return;
    }
    float p = sqrtf(p2 * (1.0f / 6.0f));
    float ip = 1.0f / p;
    float c00 = b00 * ip, c11 = b11 * ip, c22 = b22 * ip;
    float c01 = a01 * ip, c02 = a02 * ip, c12 = a12 * ip;
    float det = c00 * (c11 * c22 - c12 * c12)
              - c01 * (c01 * c22 - c12 * c02)
              + c02 * (c01 * c12 - c11 * c02);
    float r = 0.5f * det;
    r = fminf(1.0f, fmaxf(-1.0f, r));
    float phi = acosf(r) * (1.0f / 3.0f);
    float two_p = 2.0f * p;
    l2 = q + two_p * cosf(phi);                          // largest
    l0 = q + two_p * cosf(phi + 2.0943951023931953f);    // smallest
    l1 = 3.0f * q - l2 - l0;

    float m00 = a00 - l0, m11 = a11 - l0, m22 = a22 - l0;
    float x0 = a01 * a12 - a02 * m11;
    float y0 = a02 * a01 - m00 * a12;
    float z0 = m00 * m11 - a01 * a01;
    float x1 = a01 * m22 - a02 * a12;
    float y1 = a02 * a02 - m00 * m22;
    float z1 = m00 * a12 - a01 * a02;
    float x2 = m11 * m22 - a12 * a12;
    float y2 = a12 * a02 - a01 * m22;
    float z2 = a01 * a12 - m11 * a02;
    float n0 = x0 * x0 + y0 * y0 + z0 * z0;
    float n1 = x1 * x1 + y1 * y1 + z1 * z1;
    float n2 = x2 * x2 + y2 * y2 + z2 * z2;
    float bx = x0, by = y0, bz = z0, bn = n0;
    if (n1 > bn) { bx = x1; by = y1; bz = z1; bn = n1; }
    if (n2 > bn) { bx = x2; by = y2; bz = z2; bn = n2; }
    if (bn < 1e-40f) { bx = 1.0f; by = 0.0f; bz = 0.0f; bn = 1.0f; }
    float inv = rsqrtf(bn);
    vx = bx * inv; vy = by * inv; vz = bz * inv;
}

// ---------------- covariance of centered neighbor set + eig ----------------
__device__ __forceinline__ void cov_eig(const float4* __restrict__ sh,
                                        float qx, float qy, float qz,
                                        const int (&is)[KK],
                                        float &l0, float &l1, float &l2,
                                        float &vx, float &vy, float &vz) {
    float a00 = 0.f, a01 = 0.f, a02 = 0.f, a11 = 0.f, a12 = 0.f, a22 = 0.f;
#pragma unroll
    for (int t = 0; t < KK; ++t) {
        float4 nb = sh[is[t]];
        float dx = nb.x - qx, dy = nb.y - qy, dz = nb.z - qz;
        a00 = fmaf(dx, dx, a00); a01 = fmaf(dx, dy, a01); a02 = fmaf(dx, dz, a02);
        a11 = fmaf(dy, dy, a11); a12 = fmaf(dy, dz, a12); a22 = fmaf(dz, dz, a22);
    }
    eig3(a00, a01, a02, a11, a12, a22, l0, l1, l2, vx, vy, vz);
}

// ---------------- Morton cell code (12-bit, 16^3 over [-4,4]) ----------------
__device__ __forceinline__ unsigned int morton12(float x, float y, float z) {
    int ux = min(15, max(0, (int)((x + 4.0f) * 2.0f)));
    int uy = min(15, max(0, (int)((y + 4.0f) * 2.0f)));
    int uz = min(15, max(0, (int)((z + 4.0f) * 2.0f)));
    unsigned int code = 0;
#pragma unroll
    for (int b = 0; b < 4; ++b) {
        code |= ((ux >> b) & 1) << (3 * b + 0);
        code |= ((uy >> b) & 1) << (3 * b + 1);
        code |= ((uz >> b) & 1) << (3 * b + 2);
    }
    return code;
}

// ---------------- kernel 0a: histogram (32 blocks) ----------------
__global__ void __launch_bounds__(512)
hist_kernel(const float* __restrict__ pc) {
    const int b     = blockIdx.x >> 3;        // batch
    const int chunk = blockIdx.x & 7;         // eighth of the batch
    const float* base = pc + (size_t)b * NN * 3;
    const int t = threadIdx.x;

    if (blockIdx.x == 0 && t == 0) g_done = 0;   // reset arrival counter

    const int i0 = chunk * (NN / 8);
    for (int i = i0 + t; i < i0 + NN / 8; i += 512) {
        float x = base[i * 3 + 0];
        float y = base[i * 3 + 1];
        float z = base[i * 3 + 2];
        atomicAdd(&g_hist[b * NCELL + morton12(x, y, z)], 1);
    }
}

// ---------------- kernel 0b: scan offsets + re-zero hist/cnt ----------------
__global__ void __launch_bounds__(512)
scan_kernel(const float* __restrict__ pc) {
    __shared__ int part[512];
    const int b = blockIdx.x;
    const int t = threadIdx.x;

    int h[8];
    int s = 0;
#pragma unroll
    for (int u = 0; u < 8; ++u) { h[u] = g_hist[b * NCELL + t * 8 + u]; s += h[u]; }
    part[t] = s;
    __syncthreads();
    for (int o = 1; o < 512; o <<= 1) {
        int v = (t >= o) ? part[t - o] : 0;
        __syncthreads();
        part[t] += v;
        __syncthreads();
    }
    int basev = part[t] - s;
#pragma unroll
    for (int u = 0; u < 8; ++u) {
        g_off[b * NCELL + t * 8 + u] = basev;
        basev += h[u];
        g_hist[b * NCELL + t * 8 + u] = 0;   // re-zero for next replay
        g_cnt[b * NCELL + t * 8 + u] = 0;    // zero scatter counters
    }
}

// ---------------- kernel 0c: scatter (32 blocks) ----------------
__global__ void __launch_bounds__(512)
scatter_kernel(const float* __restrict__ pc) {
    const int b     = blockIdx.x >> 3;
    const int chunk = blockIdx.x & 7;
    const float* base = pc + (size_t)b * NN * 3;
    const int t = threadIdx.x;

    const int i0 = chunk * (NN / 8);
    for (int i = i0 + t; i < i0 + NN / 8; i += 512) {
        float x = base[i * 3 + 0];
        float y = base[i * 3 + 1];
        float z = base[i * 3 + 2];
        unsigned int c = morton12(x, y, z);
        int pos = g_off[b * NCELL + c] + atomicAdd(&g_cnt[b * NCELL + c], 1);
        float c2 = __fadd_rn(__fadd_rn(__fmul_rn(x, x), __fmul_rn(y, y)), __fmul_rn(z, z));
        g_sorted[b * NN + pos] = make_float4(x, y, z, c2);
        g_perm[b * NN + pos] = i;
    }
}

// ---------------- kernel 1: global kNN, outward 4-wide tile groups + seed ----
// smem layout: float4 pts[8192] | float4 boxmin[512] | float4 boxmax[512]
//              | float mds[256*16] | int mis[256*16]   (176 KB)
extern __shared__ unsigned char smem_raw[];

__global__ void __launch_bounds__(512, 1)
knn_global_kernel(const float* __restrict__ pc) {
    float4* sh     = (float4*)smem_raw;
    float4* boxmin = (float4*)(smem_raw + NN * 16);
    float4* boxmax = (float4*)(smem_raw + NN * 16 + NTILE * 16);
    float*  mds    = (float*)(smem_raw + NN * 16 + 2 * NTILE * 16);
    int*    mis    = (int*)(smem_raw + NN * 16 + 2 * NTILE * 16 + 256 * KK * 4);

    const int b = blockIdx.y;
    const float4* gs = g_sorted + b * NN;

    // stage sorted points
    for (int i = threadIdx.x; i < NN; i += 512) sh[i] = gs[i];
    __syncthreads();

    // tile AABBs (512 tiles, one per thread)
    {
        const int T = threadIdx.x;
        float4 p0 = sh[T * TSZ];
        float mnx = p0.x, mny = p0.y, mnz = p0.z;
        float mxx = p0.x, mxy = p0.y, mxz = p0.z;
#pragma unroll
        for (int u = 1; u < TSZ; ++u) {
            float4 p = sh[T * TSZ + u];
            mnx = fminf(mnx, p.x); mny = fminf(mny, p.y); mnz = fminf(mnz, p.z);
            mxx = fmaxf(mxx, p.x); mxy = fmaxf(mxy, p.y); mxz = fmaxf(mxz, p.z);
        }
        boxmin[T] = make_float4(mnx, mny, mnz, 0.f);
        boxmax[T] = make_float4(mxx, mxy, mxz, 0.f);
    }
    __syncthreads();

    const int q    = threadIdx.x & 255;       // query slot within block
    const int half = threadIdx.x >> 8;        // tile-parity this thread scans
    const int qi   = blockIdx.x * 256 + q;    // sorted index of query

    float4 qp = sh[qi];
    const float qx = qp.x, qy = qp.y, qz = qp.z, q2 = qp.w;
    const float nqx = -2.0f * qx, nqy = -2.0f * qy, nqz = -2.0f * qz;

    // --- seed: own tile has exactly 16 points -> max of their computed rank
    //     keys is a valid upper bound on the final 16th key. Ladder-free.
    float wmax = -3.4e38f;
    {
        const int jb0 = (qi >> 4) << 4;
#pragma unroll
        for (int u = 0; u < TSZ; ++u) {
            float4 c = sh[jb0 + u];
            float d = fmaf(c.x, nqx, fmaf(c.y, nqy, fmaf(c.z, nqz, c.w)));
            wmax = fmaxf(wmax, d);
        }
    }
    // prune threshold in true-d2 space, inflated for rank-key rounding slack
    float wmax_d2 = fmaf(fabsf(wmax + q2), 1e-4f, wmax + q2) + 1e-6f;

    float ds[KK];
    int   is[KK];
#pragma unroll
    for (int t = 0; t < KK; ++t) { ds[t] = 3.4e38f; is[t] = 0; }

    float bufd[BCAP];
    int   bufi[BCAP];
    int   cnt = 0;

    // warp-uniform outward order in GROUPS OF 4 same-parity tiles per side.
    // Preserves the near-first ordering (so the first flush tightens wmax
    // immediately, exactly as in the proven outward scan) while issuing 8
    // independent box loads + 4 AABB tests behind a single outer vote.
    const int own_tile = qi >> 4;
    int tb = __shfl_sync(0xffffffffu, own_tile, 16);
    int start = (tb & ~1) | half;
    int a = start, bd = start - 2;
    int sgrp = 0;

    while ((a < NTILE) | (bd >= 0)) {
        bool canA = (a < NTILE), canB = (bd >= 0);
        bool useA = canA && (!canB || ((sgrp & 1) == 0));
        ++sgrp;
        int T0, dir;
        if (useA) { T0 = a;  dir = 2;  a  += 8; }
        else      { T0 = bd; dir = -2; bd -= 8; }
        const int T1 = T0 + dir, T2 = T0 + 2 * dir, T3 = T0 + 3 * dir;
        const bool v1 = ((unsigned)T1 < NTILE);
        const bool v2 = ((unsigned)T2 < NTILE);
        const bool v3 = ((unsigned)T3 < NTILE);
        const int c1 = v1 ? T1 : T0;
        const int c2i = v2 ? T2 : T0;
        const int c3 = v3 ? T3 : T0;

        float4 bmn0 = boxmin[T0],  bmx0 = boxmax[T0];
        float4 bmn1 = boxmin[c1],  bmx1 = boxmax[c1];
        float4 bmn2 = boxmin[c2i], bmx2 = boxmax[c2i];
        float4 bmn3 = boxmin[c3],  bmx3 = boxmax[c3];

        float dx0 = fmaxf(fmaxf(bmn0.x - qx, qx - bmx0.x), 0.f);
        float dy0 = fmaxf(fmaxf(bmn0.y - qy, qy - bmx0.y), 0.f);
        float dz0 = fmaxf(fmaxf(bmn0.z - qz, qz - bmx0.z), 0.f);
        float d20 = fmaf(dx0, dx0, fmaf(dy0, dy0, dz0 * dz0));

        float dx1 = fmaxf(fmaxf(bmn1.x - qx, qx - bmx1.x), 0.f);
        float dy1 = fmaxf(fmaxf(bmn1.y - qy, qy - bmx1.y), 0.f);
        float dz1 = fmaxf(fmaxf(bmn1.z - qz, qz - bmx1.z), 0.f);
        float d21 = fmaf(dx1, dx1, fmaf(dy1, dy1, dz1 * dz1));

        float dx2 = fmaxf(fmaxf(bmn2.x - qx, qx - bmx2.x), 0.f);
        float dy2 = fmaxf(fmaxf(bmn2.y - qy, qy - bmx2.y), 0.f);
        float dz2 = fmaxf(fmaxf(bmn2.z - qz, qz - bmx2.z), 0.f);
        float d22 = fmaf(dx2, dx2, fmaf(dy2, dy2, dz2 * dz2));

        float dx3 = fmaxf(fmaxf(bmn3.x - qx, qx - bmx3.x), 0.f);
        float dy3 = fmaxf(fmaxf(bmn3.y - qy, qy - bmx3.y), 0.f);
        float dz3 = fmaxf(fmaxf(bmn3.z - qz, qz - bmx3.z), 0.f);
        float d23 = fmaf(dx3, dx3, fmaf(dy3, dy3, dz3 * dz3));

        bool h0 = d20 < wmax_d2;
        bool h1 = v1 && (d21 < wmax_d2);
        bool h2 = v2 && (d22 < wmax_d2);
        bool h3 = v3 && (d23 < wmax_d2);

        if (__any_sync(0xffffffffu, h0 | h1 | h2 | h3)) {
#pragma unroll
            for (int k = 0; k < 4; ++k) {
                bool hk = (k == 0) ? h0 : (k == 1) ? h1 : (k == 2) ? h2 : h3;
                if (__any_sync(0xffffffffu, hk)) {
                    const int jb = (T0 + k * dir) << 4;
#pragma unroll
                    for (int u = 0; u < TSZ; ++u) {
                        float4 c = sh[jb + u];
                        float d = fmaf(c.x, nqx, fmaf(c.y, nqy, fmaf(c.z, nqz, c.w)));
                        if (d <= wmax) {    // <= keeps the seed-boundary point
                            bufd[cnt] = d;
                            bufi[cnt] = jb + u;
                            ++cnt;
                        }
                    }
                    if (__any_sync(0xffffffffu, cnt > BCAP - TSZ)) {
#pragma unroll
                        for (int t = 0; t < BCAP; ++t) {
                            if (t < cnt) insert16(bufd[t], bufi[t], ds, is);
                        }
                        cnt = 0;
                        wmax = fminf(wmax, ds[KK - 1]);
                        wmax_d2 = fmaf(fabsf(wmax + q2), 1e-4f, wmax + q2) + 1e-6f;
                    }
                }
            }
        }
    }
    // drain remaining buffered hits
#pragma unroll
    for (int t = 0; t < BCAP; ++t) {
        if (t < cnt) insert16(bufd[t], bufi[t], ds, is);
    }

    // merge the two parity halves
    if (half) {
#pragma unroll
        for (int t = 0; t < KK; ++t) {
            mds[q * KK + t] = ds[t];
            mis[q * KK + t] = is[t];
        }
    }
    __syncthreads();

    if (!half) {
#pragma unroll
        for (int t = 0; t < KK; ++t) {
            float v = mds[q * KK + t];
            if (v < ds[KK - 1]) insert16(v, mis[q * KK + t], ds, is);
        }

        float l0, l1, l2, vx, vy, vz;
        cov_eig(sh, qx, qy, qz, is, l0, l1, l2, vx, vy, vz);

        const int gi = b * NN + g_perm[b * NN + qi];   // original point index
        g_nrm_abs[gi * 3 + 0] = fabsf(vx);
        g_nrm_abs[gi * 3 + 1] = fabsf(vy);
        g_nrm_abs[gi * 3 + 2] = fabsf(vz);
        g_sv[gi] = l0 / (l0 + l1 + l2);
    }
}

// ---------------- kernel 2: patch kNN + eig + loss + folded final reduction ---
__global__ void __launch_bounds__(PP, 4)
knn_patch_kernel(const float* __restrict__ pc, float* __restrict__ out) {
    __shared__ float4 shp[PP];
    __shared__ double s_n[PP];
    __shared__ double s_sv[PP];
    __shared__ bool   s_last;

    const int patch = blockIdx.x;              // 0 .. BB*NPATCH-1
    const float* base = pc + (size_t)patch * PP * 3;
    const int t = threadIdx.x;

    {
        float x = base[t * 3 + 0];
        float y = base[t * 3 + 1];
        float z = base[t * 3 + 2];
        float c2 = __fadd_rn(__fadd_rn(__fmul_rn(x, x), __fmul_rn(y, y)), __fmul_rn(z, z));
        shp[t] = make_float4(x, y, z, c2);
    }
    __syncthreads();

    float4 qp = shp[t];
    const float nqx = -2.0f * qp.x, nqy = -2.0f * qp.y, nqz = -2.0f * qp.z;

    float ds[KK];
    int   is[KK];
#pragma unroll
    for (int k = 0; k < KK; ++k) { ds[k] = 3.4e38f; is[k] = 0; }

    {
        float bufd[BCAP];
        int   bufi[BCAP];
        int   cnt = 0;
        float wmax = 3.4e38f;
        for (int j = 0; j < PP; j += 8) {
            float d[8];
#pragma unroll
            for (int u = 0; u < 8; ++u) {
                float4 c = shp[j + u];
                d[u] = fmaf(c.x, nqx, fmaf(c.y, nqy, fmaf(c.z, nqz, c.w)));
            }
            float m = fminf(fminf(fminf(d[0], d[1]), fminf(d[2], d[3])),
                            fminf(fminf(d[4], d[5]), fminf(d[6], d[7])));
            if (m < wmax) {
#pragma unroll
                for (int u = 0; u < 8; ++u) {
                    if (d[u] < wmax) { bufd[cnt] = d[u]; bufi[cnt] = j + u; ++cnt; }
                }
            }
            if (__any_sync(0xffffffffu, cnt > BCAP - 8)) {
#pragma unroll
                for (int s = 0; s < BCAP; ++s) {
                    if (s < cnt) insert16(bufd[s], bufi[s], ds, is);
                }
                cnt = 0;
                wmax = ds[KK - 1];
            }
        }
#pragma unroll
        for (int s = 0; s < BCAP; ++s) {
            if (s < cnt) insert16(bufd[s], bufi[s], ds, is);
        }
    }

    float l0, l1, l2, vx, vy, vz;
    cov_eig(shp, qp.x, qp.y, qp.z, is, l0, l1, l2, vx, vy, vz);

    const int gi = patch * PP + t;   // == flat [B, N] original index
    float svp = l0 / (l0 + l1 + l2);

    float gx = g_nrm_abs[gi * 3 + 0];
    float gy = g_nrm_abs[gi * 3 + 1];
    float gz = g_nrm_abs[gi * 3 + 2];
    float ex = fabsf(vx) - gx;
    float ey = fabsf(vy) - gy;
    float ez = fabsf(vz) - gz;
    float ln = sqrtf(ex * ex + ey * ey + ez * ez);

    float dsv = svp - g_sv[gi];
    float lsv = dsv * dsv;

    // deterministic block reduction
    s_n[t]  = (double)ln;
    s_sv[t] = (double)lsv;
    __syncthreads();
#pragma unroll
    for (int s = PP / 2; s > 0; s >>= 1) {
        if (t < s) { s_n[t] += s_n[t + s]; s_sv[t] += s_sv[t + s]; }
        __syncthreads();
    }
    if (t == 0) {
        g_pn[patch]  = s_n[0];
        g_psv[patch] = s_sv[0];
        __threadfence();
        unsigned int v = atomicAdd(&g_done, 1);
        s_last = (v == BB * NPATCH - 1);
    }
    __syncthreads();

    // last-arriving block performs the deterministic final reduction
    if (s_last) {
        if (t < BB * NPATCH) {
            s_n[t]  = __ldcg(&g_pn[t]);     // bypass L1: other SMs wrote these
            s_sv[t] = __ldcg(&g_psv[t]);
        } else {
            s_n[t] = 0.0; s_sv[t] = 0.0;
        }
        __syncthreads();
#pragma unroll
        for (int s = PP / 2; s > 0; s >>= 1) {
            if (t < s) { s_n[t] += s_n[t + s]; s_sv[t] += s_sv[t + s]; }
            __syncthreads();
        }
        if (t == 0) {
            const double inv = 1.0 / (double)(BB * NN);
            out[0] = (float)(s_n[0]  * inv);   // * W_NORMAL (=1)
            out[1] = (float)(s_sv[0] * inv);   // * W_SURFVAR (=1)
        }
    }
}

// ---------------- launcher ----------------
extern "C" void kernel_launch(void* const* d_in, const int* in_sizes, int n_in,
                              void* d_out, int out_size) {
    (void)in_sizes; (void)n_in; (void)out_size;
    const float* pc = (const float*)d_in[0];
    float* out = (float*)d_out;

    const int smem_bytes = NN * 16 + 2 * NTILE * 16 + 256 * KK * 8;  // 176 KB
    cudaFuncSetAttribute(knn_global_kernel,
                         cudaFuncAttributeMaxDynamicSharedMemorySize,
                         smem_bytes);

    hist_kernel<<<BB * 8, 512>>>(pc);
    scan_kernel<<<BB, 512>>>(pc);
    scatter_kernel<<<BB * 8, 512>>>(pc);
    dim3 g1(NN / 256, BB);
    knn_global_kernel<<<g1, 512, smem_bytes>>>(pc);
    knn_patch_kernel<<<BB * NPATCH, PP>>>(pc, out);
}

// round 17
// speedup vs baseline: 4.6249x; 1.4414x over previous
#include <cuda_runtime.h>
#include <math.h>

// Problem constants (fixed shapes per reference)
#define BB 4
#define NN 8192
#define KK 16
#define NPATCH 32
#define PP 256            // points per patch
#define NTILE 512         // 16-point tiles per batch
#define TSZ 16            // tile size
#define NCELL 4096        // 16^3 Morton cells
#define BCAP 32           // per-thread hit buffer capacity
#define NGBLK 128         // global kNN blocks (= BB * NN/256)

// ---------------- scratch (no allocations allowed) ----------------
__device__ float4 g_sorted[BB * NN];       // spatially sorted points (+|c|^2 in .w)
__device__ int    g_perm[BB * NN];         // sorted slot -> original index
__device__ float  g_pnrm[BB * NN * 3];     // |patch normal| (original index order)
__device__ float  g_psv_pt[BB * NN];       // patch surface variance per point
__device__ double g_pn[NGBLK];             // per-global-block partial normal loss
__device__ double g_psv[NGBLK];            // per-global-block partial surfvar loss
__device__ unsigned int g_done;            // global-block arrival counter
__device__ int    g_hist[BB * NCELL];      // per-batch cell histogram (zeroed after use)
__device__ int    g_off[BB * NCELL];       // per-batch exclusive cell offsets
__device__ int    g_cnt[BB * NCELL];       // per-batch scatter counters (zeroed before use)

// ---------------- sorted insertion into ascending top-16 ----------------
__device__ __forceinline__ void insert16(float v, int j, float (&ds)[KK], int (&is)[KK]) {
    bool pt = v < ds[KK - 1];
#pragma unroll
    for (int t = KK - 1; t >= 1; --t) {
        bool pm = v < ds[t - 1];
        float nv = pm ? ds[t - 1] : v;
        int   ni = pm ? is[t - 1] : j;
        ds[t] = pt ? nv : ds[t];
        is[t] = pt ? ni : is[t];
        pt = pm;
    }
    ds[0] = pt ? v : ds[0];
    is[0] = pt ? j : is[0];
}

// ---------------- analytic 3x3 symmetric eigensolver ----------------
__device__ __forceinline__ void eig3(float a00, float a01, float a02,
                                     float a11, float a12, float a22,
                                     float &l0, float &l1, float &l2,
                                     float &vx, float &vy, float &vz) {
    float q = (a00 + a11 + a22) * (1.0f / 3.0f);
    float b00 = a00 - q, b11 = a11 - q, b22 = a22 - q;
    float p1 = a01 * a01 + a02 * a02 + a12 * a12;
    float p2 = b00 * b00 + b11 * b11 + b22 * b22 + 2.0f * p1;
    if (p2 <= 1e-30f) {
        l0 = l1 = l2 = q;
        vx = 1.0f; vy = 0.0f; vz = 0.0f;
        return;
    }
    float p = sqrtf(p2 * (1.0f / 6.0f));
    float ip = 1.0f / p;
    float c00 = b00 * ip, c11 = b11 * ip, c22 = b22 * ip;
    float c01 = a01 * ip, c02 = a02 * ip, c12 = a12 * ip;
    float det = c00 * (c11 * c22 - c12 * c12)
              - c01 * (c01 * c22 - c12 * c02)
              + c02 * (c01 * c12 - c11 * c02);
    float r = 0.5f * det;
    r = fminf(1.0f, fmaxf(-1.0f, r));
    float phi = acosf(r) * (1.0f / 3.0f);
    float two_p = 2.0f * p;
    l2 = q + two_p * cosf(phi);                          // largest
    l0 = q + two_p * cosf(phi + 2.0943951023931953f);    // smallest
    l1 = 3.0f * q - l2 - l0;

    float m00 = a00 - l0, m11 = a11 - l0, m22 = a22 - l0;
    float x0 = a01 * a12 - a02 * m11;
    float y0 = a02 * a01 - m00 * a12;
    float z0 = m00 * m11 - a01 * a01;
    float x1 = a01 * m22 - a02 * a12;
    float y1 = a02 * a02 - m00 * m22;
    float z1 = m00 * a12 - a01 * a02;
    float x2 = m11 * m22 - a12 * a12;
    float y2 = a12 * a02 - a01 * m22;
    float z2 = a01 * a12 - m11 * a02;
    float n0 = x0 * x0 + y0 * y0 + z0 * z0;
    float n1 = x1 * x1 + y1 * y1 + z1 * z1;
    float n2 = x2 * x2 + y2 * y2 + z2 * z2;
    float bx = x0, by = y0, bz = z0, bn = n0;
    if (n1 > bn) { bx = x1; by = y1; bz = z1; bn = n1; }
    if (n2 > bn) { bx = x2; by = y2; bz = z2; bn = n2; }
    if (bn < 1e-40f) { bx = 1.0f; by = 0.0f; bz = 0.0f; bn = 1.0f; }
    float inv = rsqrtf(bn);
    vx = bx * inv; vy = by * inv; vz = bz * inv;
}

// ---------------- covariance of centered neighbor set + eig ----------------
__device__ __forceinline__ void cov_eig(const float4* __restrict__ sh,
                                        float qx, float qy, float qz,
                                        const int (&is)[KK],
                                        float &l0, float &l1, float &l2,
                                        float &vx, float &vy, float &vz) {
    float a00 = 0.f, a01 = 0.f, a02 = 0.f, a11 = 0.f, a12 = 0.f, a22 = 0.f;
#pragma unroll
    for (int t = 0; t < KK; ++t) {
        float4 nb = sh[is[t]];
        float dx = nb.x - qx, dy = nb.y - qy, dz = nb.z - qz;
        a00 = fmaf(dx, dx, a00); a01 = fmaf(dx, dy, a01); a02 = fmaf(dx, dz, a02);
        a11 = fmaf(dy, dy, a11); a12 = fmaf(dy, dz, a12); a22 = fmaf(dz, dz, a22);
    }
    eig3(a00, a01, a02, a11, a12, a22, l0, l1, l2, vx, vy, vz);
}

// ---------------- Morton cell code (12-bit, 16^3 over [-4,4]) ----------------
__device__ __forceinline__ unsigned int morton12(float x, float y, float z) {
    int ux = min(15, max(0, (int)((x + 4.0f) * 2.0f)));
    int uy = min(15, max(0, (int)((y + 4.0f) * 2.0f)));
    int uz = min(15, max(0, (int)((z + 4.0f) * 2.0f)));
    unsigned int code = 0;
#pragma unroll
    for (int b = 0; b < 4; ++b) {
        code |= ((ux >> b) & 1) << (3 * b + 0);
        code |= ((uy >> b) & 1) << (3 * b + 1);
        code |= ((uz >> b) & 1) << (3 * b + 2);
    }
    return code;
}

// ---------------- kernel 0a: combo = histogram (16 blk) + patch kNN (64 blk) --
// Patch part is independent of the global pass: it stores |patch normal| and
// patch surface variance per point; the global kernel combines them into the
// loss. 2 patches per 512-thread block.
__global__ void __launch_bounds__(512)
combo_kernel(const float* __restrict__ pc) {
    const int t = threadIdx.x;

    if (blockIdx.x == 0 && t == 0) g_done = 0;   // reset arrival counter

    if (blockIdx.x < 16) {
        // ---- histogram part ----
        const int b     = blockIdx.x >> 2;
        const int chunk = blockIdx.x & 3;
        const float* base = pc + (size_t)b * NN * 3;
        const int i0 = chunk * (NN / 4);
        for (int i = i0 + t; i < i0 + NN / 4; i += 512) {
            float x = base[i * 3 + 0];
            float y = base[i * 3 + 1];
            float z = base[i * 3 + 2];
            atomicAdd(&g_hist[b * NCELL + morton12(x, y, z)], 1);
        }
        return;
    }

    // ---- patch part: 2 patches per block ----
    __shared__ float4 shp[2][PP];
    const int sub  = t >> 8;                  // 0/1: which patch in this block
    const int tl   = t & 255;                 // thread within patch
    const int patch = (blockIdx.x - 16) * 2 + sub;   // 0 .. 127
    const float* base = pc + (size_t)patch * PP * 3;

    {
        float x = base[tl * 3 + 0];
        float y = base[tl * 3 + 1];
        float z = base[tl * 3 + 2];
        float c2 = __fadd_rn(__fadd_rn(__fmul_rn(x, x), __fmul_rn(y, y)), __fmul_rn(z, z));
        shp[sub][tl] = make_float4(x, y, z, c2);
    }
    __syncthreads();

    const float4* sp = shp[sub];
    float4 qp = sp[tl];
    const float nqx = -2.0f * qp.x, nqy = -2.0f * qp.y, nqz = -2.0f * qp.z;

    float ds[KK];
    int   is[KK];
#pragma unroll
    for (int k = 0; k < KK; ++k) { ds[k] = 3.4e38f; is[k] = 0; }

    {
        float bufd[BCAP];
        int   bufi[BCAP];
        int   cnt = 0;
        float wmax = 3.4e38f;
        for (int j = 0; j < PP; j += 8) {
            float d[8];
#pragma unroll
            for (int u = 0; u < 8; ++u) {
                float4 c = sp[j + u];
                d[u] = fmaf(c.x, nqx, fmaf(c.y, nqy, fmaf(c.z, nqz, c.w)));
            }
            float m = fminf(fminf(fminf(d[0], d[1]), fminf(d[2], d[3])),
                            fminf(fminf(d[4], d[5]), fminf(d[6], d[7])));
            if (m < wmax) {
#pragma unroll
                for (int u = 0; u < 8; ++u) {
                    if (d[u] < wmax) { bufd[cnt] = d[u]; bufi[cnt] = j + u; ++cnt; }
                }
            }
            if (__any_sync(0xffffffffu, cnt > BCAP - 8)) {
#pragma unroll
                for (int s = 0; s < BCAP; ++s) {
                    if (s < cnt) insert16(bufd[s], bufi[s], ds, is);
                }
                cnt = 0;
                wmax = ds[KK - 1];
            }
        }
#pragma unroll
        for (int s = 0; s < BCAP; ++s) {
            if (s < cnt) insert16(bufd[s], bufi[s], ds, is);
        }
    }

    float l0, l1, l2, vx, vy, vz;
    cov_eig(sp, qp.x, qp.y, qp.z, is, l0, l1, l2, vx, vy, vz);

    const int gi = patch * PP + tl;   // flat [B, N] original index
    g_pnrm[gi * 3 + 0] = fabsf(vx);
    g_pnrm[gi * 3 + 1] = fabsf(vy);
    g_pnrm[gi * 3 + 2] = fabsf(vz);
    g_psv_pt[gi] = l0 / (l0 + l1 + l2);
}

// ---------------- kernel 0b: scan offsets + re-zero hist/cnt ----------------
__global__ void __launch_bounds__(512)
scan_kernel(const float* __restrict__ pc) {
    __shared__ int part[512];
    const int b = blockIdx.x;
    const int t = threadIdx.x;

    int h[8];
    int s = 0;
#pragma unroll
    for (int u = 0; u < 8; ++u) { h[u] = g_hist[b * NCELL + t * 8 + u]; s += h[u]; }
    part[t] = s;
    __syncthreads();
    for (int o = 1; o < 512; o <<= 1) {
        int v = (t >= o) ? part[t - o] : 0;
        __syncthreads();
        part[t] += v;
        __syncthreads();
    }
    int basev = part[t] - s;
#pragma unroll
    for (int u = 0; u < 8; ++u) {
        g_off[b * NCELL + t * 8 + u] = basev;
        basev += h[u];
        g_hist[b * NCELL + t * 8 + u] = 0;   // re-zero for next replay
        g_cnt[b * NCELL + t * 8 + u] = 0;    // zero scatter counters
    }
}

// ---------------- kernel 0c: scatter (16 blocks) ----------------
__global__ void __launch_bounds__(512)
scatter_kernel(const float* __restrict__ pc) {
    const int b     = blockIdx.x >> 2;
    const int chunk = blockIdx.x & 3;
    const float* base = pc + (size_t)b * NN * 3;
    const int t = threadIdx.x;

    const int i0 = chunk * (NN / 4);
    for (int i = i0 + t; i < i0 + NN / 4; i += 512) {
        float x = base[i * 3 + 0];
        float y = base[i * 3 + 1];
        float z = base[i * 3 + 2];
        unsigned int c = morton12(x, y, z);
        int pos = g_off[b * NCELL + c] + atomicAdd(&g_cnt[b * NCELL + c], 1);
        float c2 = __fadd_rn(__fadd_rn(__fmul_rn(x, x), __fmul_rn(y, y)), __fmul_rn(z, z));
        g_sorted[b * NN + pos] = make_float4(x, y, z, c2);
        g_perm[b * NN + pos] = i;
    }
}

// ---------------- kernel 1: global kNN (R14 scan verbatim) + loss + reduce ---
// smem: float4 pts[8192] | float4 boxmin[512] | float4 boxmax[512]
//       | float mds[256*16] | int mis[256*16] | double s_n[256] | s_sv[256]
extern __shared__ unsigned char smem_raw[];

__global__ void __launch_bounds__(512, 1)
knn_global_kernel(const float* __restrict__ pc, float* __restrict__ out) {
    float4* sh     = (float4*)smem_raw;
    float4* boxmin = (float4*)(smem_raw + NN * 16);
    float4* boxmax = (float4*)(smem_raw + NN * 16 + NTILE * 16);
    float*  mds    = (float*)(smem_raw + NN * 16 + 2 * NTILE * 16);
    int*    mis    = (int*)(smem_raw + NN * 16 + 2 * NTILE * 16 + 256 * KK * 4);
    double* s_n    = (double*)(smem_raw + NN * 16 + 2 * NTILE * 16 + 256 * KK * 8);
    double* s_sv   = s_n + 256;
    __shared__ bool s_last;

    const int b = blockIdx.y;
    const float4* gs = g_sorted + b * NN;

    // stage sorted points
    for (int i = threadIdx.x; i < NN; i += 512) sh[i] = gs[i];
    __syncthreads();

    // tile AABBs (512 tiles, one per thread)
    {
        const int T = threadIdx.x;
        float4 p0 = sh[T * TSZ];
        float mnx = p0.x, mny = p0.y, mnz = p0.z;
        float mxx = p0.x, mxy = p0.y, mxz = p0.z;
#pragma unroll
        for (int u = 1; u < TSZ; ++u) {
            float4 p = sh[T * TSZ + u];
            mnx = fminf(mnx, p.x); mny = fminf(mny, p.y); mnz = fminf(mnz, p.z);
            mxx = fmaxf(mxx, p.x); mxy = fmaxf(mxy, p.y); mxz = fmaxf(mxz, p.z);
        }
        boxmin[T] = make_float4(mnx, mny, mnz, 0.f);
        boxmax[T] = make_float4(mxx, mxy, mxz, 0.f);
    }
    __syncthreads();

    const int q    = threadIdx.x & 255;       // query slot within block
    const int half = threadIdx.x >> 8;        // tile-parity this thread scans
    const int qi   = blockIdx.x * 256 + q;    // sorted index of query

    float4 qp = sh[qi];
    const float qx = qp.x, qy = qp.y, qz = qp.z, q2 = qp.w;
    const float nqx = -2.0f * qx, nqy = -2.0f * qy, nqz = -2.0f * qz;

    // --- seed: own tile has exactly 16 points -> max of their computed rank
    //     keys is a valid upper bound on the final 16th key. Ladder-free.
    float wmax = -3.4e38f;
    {
        const int jb0 = (qi >> 4) << 4;
#pragma unroll
        for (int u = 0; u < TSZ; ++u) {
            float4 c = sh[jb0 + u];
            float d = fmaf(c.x, nqx, fmaf(c.y, nqy, fmaf(c.z, nqz, c.w)));
            wmax = fmaxf(wmax, d);
        }
    }
    // prune threshold in true-d2 space, inflated for rank-key rounding slack
    float wmax_d2 = fmaf(fabsf(wmax + q2), 1e-4f, wmax + q2) + 1e-6f;

    float ds[KK];
    int   is[KK];
#pragma unroll
    for (int t = 0; t < KK; ++t) { ds[t] = 3.4e38f; is[t] = 0; }

    float bufd[BCAP];
    int   bufi[BCAP];
    int   cnt = 0;

    // warp-uniform outward tile order, restricted to this thread's parity
    const int own_tile = qi >> 4;
    int tb = __shfl_sync(0xffffffffu, own_tile, 16);
    int start = (tb & ~1) | half;
    int a = start, bd = start - 2;

    for (int s = 0; s < NTILE / 2; ++s) {
        int T;
        bool canA = (a < NTILE), canB = (bd >= 0);
        if (canA && (!canB || ((s & 1) == 0))) { T = a; a += 2; }
        else                                   { T = bd; bd -= 2; }

        // conservative AABB lower bound on d2 for every point in tile T
        float4 bmn = boxmin[T];
        float4 bmx = boxmax[T];
        float dx = fmaxf(fmaxf(bmn.x - qx, qx - bmx.x), 0.f);
        float dy = fmaxf(fmaxf(bmn.y - qy, qy - bmx.y), 0.f);
        float dz = fmaxf(fmaxf(bmn.z - qz, qz - bmx.z), 0.f);
        float d2b = fmaf(dx, dx, fmaf(dy, dy, dz * dz));
        bool hit = d2b < wmax_d2;

        if (__any_sync(0xffffffffu, hit)) {
            const int jb = T << 4;
#pragma unroll
            for (int u = 0; u < TSZ; ++u) {
                float4 c = sh[jb + u];
                float d = fmaf(c.x, nqx, fmaf(c.y, nqy, fmaf(c.z, nqz, c.w)));
                if (d <= wmax) {            // <= keeps the seed-boundary point
                    bufd[cnt] = d;
                    bufi[cnt] = jb + u;
                    ++cnt;
                }
            }
            if (__any_sync(0xffffffffu, cnt > BCAP - TSZ)) {
#pragma unroll
                for (int t = 0; t < BCAP; ++t) {
                    if (t < cnt) insert16(bufd[t], bufi[t], ds, is);
                }
                cnt = 0;
                wmax = fminf(wmax, ds[KK - 1]);
                wmax_d2 = fmaf(fabsf(wmax + q2), 1e-4f, wmax + q2) + 1e-6f;
            }
        }
    }
    // drain remaining buffered hits
#pragma unroll
    for (int t = 0; t < BCAP; ++t) {
        if (t < cnt) insert16(bufd[t], bufi[t], ds, is);
    }

    // merge the two parity halves
    if (half) {
#pragma unroll
        for (int t = 0; t < KK; ++t) {
            mds[q * KK + t] = ds[t];
            mis[q * KK + t] = is[t];
        }
    }
    __syncthreads();

    // half==0 threads: finish kNN, eig, and per-point loss terms
    double ln_d = 0.0, lsv_d = 0.0;
    if (!half) {
#pragma unroll
        for (int t = 0; t < KK; ++t) {
            float v = mds[q * KK + t];
            if (v < ds[KK - 1]) insert16(v, mis[q * KK + t], ds, is);
        }

        float l0, l1, l2, vx, vy, vz;
        cov_eig(sh, qx, qy, qz, is, l0, l1, l2, vx, vy, vz);

        const int gi = b * NN + g_perm[b * NN + qi];   // original point index
        float sv_g = l0 / (l0 + l1 + l2);

        float px = g_pnrm[gi * 3 + 0];
        float py = g_pnrm[gi * 3 + 1];
        float pz = g_pnrm[gi * 3 + 2];
        float ex = px - fabsf(vx);
        float ey = py - fabsf(vy);
        float ez = pz - fabsf(vz);
        ln_d = (double)sqrtf(ex * ex + ey * ey + ez * ez);

        float dsv = g_psv_pt[gi] - sv_g;
        lsv_d = (double)(dsv * dsv);
    }

    // block partial reduction over the 256 queries (fixed tree)
    if (!half) { s_n[q] = ln_d; s_sv[q] = lsv_d; }
    __syncthreads();
    {
        const int t = threadIdx.x;
#pragma unroll
        for (int s = 128; s > 0; s >>= 1) {
            if (t < s) { s_n[t] += s_n[t + s]; s_sv[t] += s_sv[t + s]; }
            __syncthreads();
        }
        const int blin = b * (NN / 256) + blockIdx.x;   // 0..127
        if (t == 0) {
            g_pn[blin]  = s_n[0];
            g_psv[blin] = s_sv[0];
            __threadfence();
            unsigned int v = atomicAdd(&g_done, 1);
            s_last = (v == NGBLK - 1);
        }
    }
    __syncthreads();

    // last-arriving block performs the deterministic final reduction
    if (s_last) {
        const int t = threadIdx.x;
        if (t < NGBLK) {
            s_n[t]  = __ldcg(&g_pn[t]);
            s_sv[t] = __ldcg(&g_psv[t]);
        } else if (t < 256) {
            s_n[t] = 0.0; s_sv[t] = 0.0;
        }
        __syncthreads();
#pragma unroll
        for (int s = 128; s > 0; s >>= 1) {
            if (t < s) { s_n[t] += s_n[t + s]; s_sv[t] += s_sv[t + s]; }
            __syncthreads();
        }
        if (t == 0) {
            const double inv = 1.0 / (double)(BB * NN);
            out[0] = (float)(s_n[0]  * inv);   // * W_NORMAL (=1)
            out[1] = (float)(s_sv[0] * inv);   // * W_SURFVAR (=1)
        }
    }
}

// ---------------- launcher ----------------
extern "C" void kernel_launch(void* const* d_in, const int* in_sizes, int n_in,
                              void* d_out, int out_size) {
    (void)in_sizes; (void)n_in; (void)out_size;
    const float* pc = (const float*)d_in[0];
    float* out = (float*)d_out;

    // 128K pts + 16K boxes + 32K merge + 4K reduce = 180.5 KB
    const int smem_bytes = NN * 16 + 2 * NTILE * 16 + 256 * KK * 8 + 2 * 256 * 8;
    cudaFuncSetAttribute(knn_global_kernel,
                         cudaFuncAttributeMaxDynamicSharedMemorySize,
                         smem_bytes);

    combo_kernel<<<16 + 64, 512>>>(pc);          // hist + patch kNN
    scan_kernel<<<BB, 512>>>(pc);
    scatter_kernel<<<BB * 4, 512>>>(pc);
    dim3 g1(NN / 256, BB);
    knn_global_kernel<<<g1, 512, smem_bytes>>>(pc, out);
}